// round 16
// baseline (speedup 1.0000x reference)
#include <cuda_runtime.h>
#include <math.h>

#define NUM_B 8
#define NUM_A 131072
#define NUM_C 4
#define NUM_M 64
#define BLOCK 256
#define APT 4                               // anchors per thread, STRIDED
#define GRIDX (NUM_A / (BLOCK * APT))       // 128
#define NBLOCKS (GRIDX * NUM_B)             // 1024
#define TPS (GRIDX * BLOCK)                 // 32768 threads per sample
#define NBKT 64                             // 8-px x-buckets over [0, 512)

// Per-block partials: [cls_sum, xy_sum, ang_sum, num_pos]. Plain stores each run.
__device__ float4 g_part[NBLOCKS];
__device__ unsigned int g_count = 0;   // self-resetting completion counter

#define ADD_F32X2(out, a, b) \
    asm("add.rn.f32x2 %0, %1, %2;" : "=l"(out) : "l"(a), "l"(b))
#define MUL_F32X2(out, a, b) \
    asm("mul.rn.f32x2 %0, %1, %2;" : "=l"(out) : "l"(a), "l"(b))
#define FMA_F32X2(out, a, b, c) \
    asm("fma.rn.f32x2 %0, %1, %2, %3;" : "=l"(out) : "l"(a), "l"(b), "l"(c))
#define PACK_F32X2(out, lo, hi) \
    asm("mov.b64 %0, {%1, %2};" : "=l"(out) : "r"(lo), "r"(hi))

__global__ __launch_bounds__(BLOCK) void focal_fused_kernel(
    const float* __restrict__ cls,   // (B, A, C)
    const float* __restrict__ reg,   // (B, A, 3)
    const float* __restrict__ anc,   // (A, 3)
    const float* __restrict__ ann,   // (B, M, 4)
    float* __restrict__ out)         // (3,)
{
    // Original-order arrays (exact epilogue recompute):
    __shared__ __align__(16) float s_pair[NUM_M * 2]; // (-x0,-x1,-y0,-y1) by ORIG pair
    __shared__ float s_al[NUM_M];
    __shared__ float s_lb[NUM_M];
    // Sort machinery:
    __shared__ float s_un[NUM_M];      // unsorted x (+1e18 if invalid)
    __shared__ float s_tnx[NUM_M];     // ranked -x
    __shared__ float s_tny[NUM_M];     // ranked -y
    __shared__ int   s_torig[NUM_M];   // ranked original index
    __shared__ unsigned s_lut[NBKT];   // per-bucket: lo | (hi << 8)
    // Scan pairs (sorted order): (-x_{2p}, -x_{2p+1}, -y_{2p}, -y_{2p+1})
    __shared__ __align__(16) float4 s_sp[NUM_M / 2];

    const int b   = blockIdx.y;
    const int tid = threadIdx.x;

    float xv = 0.0f, nx = 0.0f, ny = 0.0f;
    if (tid < NUM_M) {
        const float* a4 = ann + ((size_t)b * NUM_M + tid) * 4;
        float x = a4[0], y = a4[1], al = a4[2], lb = a4[3];
        bool valid = (lb != -1.0f);
        // invalid -> +1e18 sort key (sorts last, outside every bucket window),
        // -1e18 coords (d2 ~ 1e36, never wins, never passes thresholds).
        const int j = tid >> 1, slot = tid & 1;
        s_pair[4 * j + slot]     = valid ? -x : -1e18f;
        s_pair[4 * j + 2 + slot] = valid ? -y : -1e18f;
        s_al[tid] = al;
        s_lb[tid] = lb;
        xv = valid ? x : 1e18f;
        nx = valid ? -x : -1e18f;
        ny = valid ? -y : -1e18f;
        s_un[tid] = xv;
    }
    __syncthreads();

    // One fused pass (threads 0..63): rank-sort by x (stable) + bucket LUT.
    // Bucket g covers anchors with ax in [8g, 8g+8); its candidate window
    // [8g-30, 8g+38) is a superset of every such anchor's [ax-30, ax+30).
    if (tid < NUM_M) {
        const float tlo = tid * 8.0f - 30.0f;
        const float thi = tid * 8.0f + 38.0f;
        int r = 0, lo = 0, hi = 0;
        #pragma unroll
        for (int j = 0; j < NUM_M; j++) {
            float xj = s_un[j];                       // broadcast read
            r  += ((xj < xv) || (xj == xv && j < tid)) ? 1 : 0;
            lo += (xj < tlo) ? 1 : 0;
            hi += (xj < thi) ? 1 : 0;
        }
        s_tnx[r]   = nx;
        s_tny[r]   = ny;
        s_torig[r] = tid;
        s_lut[tid] = (unsigned)lo | ((unsigned)hi << 8);
    }
    __syncthreads();

    // Pack sorted pairs for the 128-bit scan.
    if (tid < NUM_M / 2) {
        s_sp[tid] = make_float4(s_tnx[2 * tid], s_tnx[2 * tid + 1],
                                s_tny[2 * tid], s_tny[2 * tid + 1]);
    }
    __syncthreads();

    const int t = blockIdx.x * BLOCK + tid;   // thread index within sample
    const unsigned KMASK = 0xffffffc0u;
    float v0 = 0.0f, v1 = 0.0f, v2 = 0.0f, v3 = 0.0f;

    // ---- batched prefetch: ALL anchor coords + ALL cls vectors up front ----
    // (16 independent loads in flight -> one latency exposure, not four)
    float ax[APT], ay[APT], aal[APT];
    float4 c4[APT];
    #pragma unroll
    for (int k = 0; k < APT; k++) {
        const int a = t + k * TPS;
        ax[k]  = anc[3 * a + 0];
        ay[k]  = anc[3 * a + 1];
        aal[k] = anc[3 * a + 2];
        c4[k]  = *(const float4*)(cls + ((size_t)b * NUM_A + a) * NUM_C);
    }

    // Window lookups for all 4 anchors (independent LDS chains overlap).
    int p0v[APT], tripsv[APT];
    unsigned long long axx[APT], ayy[APT];
    #pragma unroll
    for (int k = 0; k < APT; k++) {
        unsigned xb = __float_as_uint(ax[k]), yb = __float_as_uint(ay[k]);
        PACK_F32X2(axx[k], xb, xb);
        PACK_F32X2(ayy[k], yb, yb);
        const int g = min((int)(ax[k] * 0.125f), NBKT - 1);
        const unsigned lut = s_lut[g];
        const int lo = (int)(lut & 0xffu);
        const int hi = (int)(lut >> 8);
        p0v[k]    = lo >> 1;
        tripsv[k] = ((hi + 1) >> 1) - p0v[k];   // pairs covering [lo, hi)
    }

    #pragma unroll 1
    for (int k = 0; k < APT; k++) {
        const int a = t + k * TPS;

        // Pruned argmin via bit-packed keys (positive-float bits u32-ordered;
        // low 6 bits carry the SORTED index; winner remapped via s_torig).
        // Superset-safe: every annotation with d<30 lies in the bucket window;
        // if the winner's exact d2 >= 900 the anchor is background and the
        // winner's identity never reaches the output.
        unsigned bestkey = 0xffffffffu;
        const int p0 = p0v[k], trips = tripsv[k];
        const ulonglong2* sp = (const ulonglong2*)s_sp;
        for (int j = 0; j < trips; j++) {       // SIMT predication = warp-max
            ulonglong2 q = sp[p0 + j];          // (-x0,-x1), (-y0,-y1)
            unsigned long long dxp, dyp, tp, d2p;
            ADD_F32X2(dxp, axx[k], q.x);        // (ax-x0, ax-x1)
            ADD_F32X2(dyp, ayy[k], q.y);
            MUL_F32X2(tp, dxp, dxp);
            FMA_F32X2(d2p, dyp, dyp, tp);       // == fmaf(dy,dy,dx*dx) per lane
            unsigned sj = (unsigned)(2 * (p0 + j));
            unsigned klo = ((unsigned)d2p & KMASK) | sj;
            unsigned khi = ((unsigned)(d2p >> 32) & KMASK) | (sj + 1u);
            bestkey = min(bestkey, min(klo, khi));
        }
        const int bestm = s_torig[bestkey & 63u];   // sorted -> original index

        // ---- epilogue: recompute EXACT values from original-order arrays ----
        const int bj = bestm >> 1, bslot = bestm & 1;
        const float bx  = -s_pair[4 * bj + bslot];
        const float by  = -s_pair[4 * bj + 2 + bslot];
        const float bal = s_al[bestm];
        const float ddx = ax[k] - bx;
        const float ddy = ay[k] - by;
        const float best = fmaf(ddy, ddy, ddx * ddx);
        const float dang = fabsf(aal[k] - bal);

        // sqrt-free thresholds: dxy<20 <=> d2<400 ; dxy>=30 <=> d2>=900
        const bool positive   = (best < 400.0f) && (dang < 15.0f);
        const bool background = (best >= 900.0f) || (dang >= 22.5f);
        const bool care       = positive || background;

        if (care) {
            int label = positive ? min(max((int)s_lb[bestm], 0), NUM_C - 1) : -1;
            float cv[4] = {c4[k].x, c4[k].y, c4[k].z, c4[k].w};
            #pragma unroll
            for (int c = 0; c < NUM_C; c++) {
                float p = fminf(fmaxf(cv[c], 1e-4f), 1.0f - 1e-4f);
                bool is1 = (c == label);
                // t==1: w = 0.95*(1-p)^2, bce = -log(p)
                // t==0: w = 0.05*p^2,     bce = -log(1-p)
                float q = is1 ? (1.0f - p) : p;
                float w = (is1 ? 0.95f : 0.05f) * q * q;
                float bce = -__logf(1.0f - q);
                v0 = fmaf(w, bce, v0);
            }
        }

        if (positive) {
            const float* r3 = reg + ((size_t)b * NUM_A + a) * 3;
            float tx = bx  - ax[k];
            float ty = by  - ay[k];
            float ta = bal - aal[k];
            float dxr = fabsf(tx - r3[0]);
            float dyr = fabsf(ty - r3[1]);
            const float inv9 = 1.0f / 9.0f;
            float lx = (dxr <= inv9) ? (4.5f * dxr * dxr) : (dxr - 0.5f * inv9);
            float ly = (dyr <= inv9) ? (4.5f * dyr * dyr) : (dyr - 0.5f * inv9);
            v1 += lx + ly;
            v2 += fmaxf((fabsf(ta - r3[2]) - 10.0f) * 0.2f, 0.0f);
            v3 += 1.0f;
        }
    }

    // ---- block reduction: 4 quantities ----
    #pragma unroll
    for (int o = 16; o > 0; o >>= 1) {
        v0 += __shfl_down_sync(0xffffffffu, v0, o);
        v1 += __shfl_down_sync(0xffffffffu, v1, o);
        v2 += __shfl_down_sync(0xffffffffu, v2, o);
        v3 += __shfl_down_sync(0xffffffffu, v3, o);
    }
    __shared__ float red[BLOCK / 32][4];
    const int wid = tid >> 5, lid = tid & 31;
    if (lid == 0) {
        red[wid][0] = v0; red[wid][1] = v1; red[wid][2] = v2; red[wid][3] = v3;
    }
    __syncthreads();
    if (tid < 4) {
        float s = 0.0f;
        #pragma unroll
        for (int w = 0; w < BLOCK / 32; w++) s += red[w][tid];
        ((float*)&g_part[(size_t)b * GRIDX + blockIdx.x])[tid] = s;
        __threadfence();   // publish partials before the ticket increment
    }
    __syncthreads();

    // ---- last-block finalize (fused, no extra launches) ----
    __shared__ bool is_last;
    if (tid == 0) {
        unsigned v = atomicAdd(&g_count, 1u);
        is_last = (v == NBLOCKS - 1);
    }
    __syncthreads();
    if (!is_last) return;
    if (tid == 0) g_count = 0;   // reset for next graph replay

    // 8 warps: warp w reduces sample b=w over its 128 partials.
    __shared__ float s_res[NUM_B][3];
    const int w = tid >> 5, l = tid & 31;
    float4 acc = make_float4(0.f, 0.f, 0.f, 0.f);
    #pragma unroll
    for (int kk = 0; kk < GRIDX / 32; kk++) {
        float4 p = g_part[(size_t)w * GRIDX + l + 32 * kk];
        acc.x += p.x; acc.y += p.y; acc.z += p.z; acc.w += p.w;
    }
    #pragma unroll
    for (int o = 16; o > 0; o >>= 1) {
        acc.x += __shfl_down_sync(0xffffffffu, acc.x, o);
        acc.y += __shfl_down_sync(0xffffffffu, acc.y, o);
        acc.z += __shfl_down_sync(0xffffffffu, acc.z, o);
        acc.w += __shfl_down_sync(0xffffffffu, acc.w, o);
    }
    if (l == 0) {
        float denom = fmaxf(acc.w, 1.0f);
        s_res[w][0] = acc.x / denom;
        s_res[w][1] = acc.y / (2.0f * denom);
        s_res[w][2] = acc.z / denom;
    }
    __syncthreads();
    if (tid == 0) {
        float c = 0.f, x = 0.f, an = 0.f;
        #pragma unroll
        for (int bb = 0; bb < NUM_B; bb++) {
            c += s_res[bb][0]; x += s_res[bb][1]; an += s_res[bb][2];
        }
        out[0] = c  * (1.0f / NUM_B);
        out[1] = x  * (1.0f / NUM_B);
        out[2] = an * (1.0f / NUM_B);
    }
}

extern "C" void kernel_launch(void* const* d_in, const int* in_sizes, int n_in,
                              void* d_out, int out_size) {
    (void)in_sizes; (void)n_in; (void)out_size;
    const float* cls = (const float*)d_in[0];   // (B, A, C)
    const float* reg = (const float*)d_in[1];   // (B, A, 3)
    const float* anc = (const float*)d_in[2];   // (1, A, 3)
    const float* ann = (const float*)d_in[3];   // (B, M, 4)
    float* out = (float*)d_out;

    dim3 grid(GRIDX, NUM_B);
    focal_fused_kernel<<<grid, BLOCK>>>(cls, reg, anc, ann, out);
}

// round 17
// speedup vs baseline: 1.2733x; 1.2733x over previous
#include <cuda_runtime.h>
#include <math.h>

#define NUM_B 8
#define NUM_A 131072
#define NUM_C 4
#define NUM_M 64
#define BLOCK 256
#define APT 4                               // anchors per thread, STRIDED
#define GRIDX (NUM_A / (BLOCK * APT))       // 128
#define NBLOCKS (GRIDX * NUM_B)             // 1024
#define TPS (GRIDX * BLOCK)                 // 32768 threads per sample
#define NBKT 64                             // 8-px x-buckets over [0, 512)

// Per-block partials: [cls_sum, xy_sum, ang_sum, num_pos]. Plain stores each run.
__device__ float4 g_part[NBLOCKS];
__device__ unsigned int g_count = 0;   // self-resetting completion counter

#define ADD_F32X2(out, a, b) \
    asm("add.rn.f32x2 %0, %1, %2;" : "=l"(out) : "l"(a), "l"(b))
#define MUL_F32X2(out, a, b) \
    asm("mul.rn.f32x2 %0, %1, %2;" : "=l"(out) : "l"(a), "l"(b))
#define FMA_F32X2(out, a, b, c) \
    asm("fma.rn.f32x2 %0, %1, %2, %3;" : "=l"(out) : "l"(a), "l"(b), "l"(c))
#define PACK_F32X2(out, lo, hi) \
    asm("mov.b64 %0, {%1, %2};" : "=l"(out) : "r"(lo), "r"(hi))

__global__ __launch_bounds__(BLOCK) void focal_fused_kernel(
    const float* __restrict__ cls,   // (B, A, C)
    const float* __restrict__ reg,   // (B, A, 3)
    const float* __restrict__ anc,   // (A, 3)
    const float* __restrict__ ann,   // (B, M, 4)
    float* __restrict__ out)         // (3,)
{
    // Original-order arrays (exact epilogue recompute):
    __shared__ __align__(16) float s_pair[NUM_M * 2]; // (-x0,-x1,-y0,-y1) by ORIG pair
    __shared__ float s_al[NUM_M];
    __shared__ float s_lb[NUM_M];
    // Sort machinery:
    __shared__ float s_un[NUM_M];      // unsorted x (+1e18 if invalid)
    __shared__ float s_tnx[NUM_M];     // ranked -x
    __shared__ float s_tny[NUM_M];     // ranked -y
    __shared__ int   s_torig[NUM_M];   // ranked original index
    __shared__ unsigned s_lut[NBKT];   // per-bucket: lo | (hi << 8)
    // Scan pairs (sorted order): (-x_{2p}, -x_{2p+1}, -y_{2p}, -y_{2p+1})
    __shared__ __align__(16) float4 s_sp[NUM_M / 2];

    const int b   = blockIdx.y;
    const int tid = threadIdx.x;

    float xv = 0.0f, nx = 0.0f, ny = 0.0f;
    if (tid < NUM_M) {
        const float* a4 = ann + ((size_t)b * NUM_M + tid) * 4;
        float x = a4[0], y = a4[1], al = a4[2], lb = a4[3];
        bool valid = (lb != -1.0f);
        // invalid -> +1e18 sort key (sorts last, outside every bucket window),
        // -1e18 coords (d2 ~ 1e36, never wins, never passes thresholds).
        const int j = tid >> 1, slot = tid & 1;
        s_pair[4 * j + slot]     = valid ? -x : -1e18f;
        s_pair[4 * j + 2 + slot] = valid ? -y : -1e18f;
        s_al[tid] = al;
        s_lb[tid] = lb;
        xv = valid ? x : 1e18f;
        nx = valid ? -x : -1e18f;
        ny = valid ? -y : -1e18f;
        s_un[tid] = xv;
    }
    __syncthreads();

    // One fused pass (threads 0..63): rank-sort by x (stable) + bucket LUT.
    // Bucket g covers anchors with ax in [8g, 8g+8); its candidate window
    // [8g-30, 8g+38) is a superset of every such anchor's [ax-30, ax+30).
    if (tid < NUM_M) {
        const float tlo = tid * 8.0f - 30.0f;
        const float thi = tid * 8.0f + 38.0f;
        int r = 0, lo = 0, hi = 0;
        #pragma unroll
        for (int j = 0; j < NUM_M; j++) {
            float xj = s_un[j];                       // broadcast read
            r  += ((xj < xv) || (xj == xv && j < tid)) ? 1 : 0;
            lo += (xj < tlo) ? 1 : 0;
            hi += (xj < thi) ? 1 : 0;
        }
        s_tnx[r]   = nx;
        s_tny[r]   = ny;
        s_torig[r] = tid;
        s_lut[tid] = (unsigned)lo | ((unsigned)hi << 8);
    }
    __syncthreads();

    // Pack sorted pairs for the 128-bit scan.
    if (tid < NUM_M / 2) {
        s_sp[tid] = make_float4(s_tnx[2 * tid], s_tnx[2 * tid + 1],
                                s_tny[2 * tid], s_tny[2 * tid + 1]);
    }
    __syncthreads();

    const int t = blockIdx.x * BLOCK + tid;   // thread index within sample
    const unsigned KMASK = 0xffffffc0u;
    float v0 = 0.0f, v1 = 0.0f, v2 = 0.0f, v3 = 0.0f;

    // ---- batched prefetch: ALL anchor coords + ALL cls vectors up front.
    // The APT loop below is FULLY UNROLLED so every per-k array resolves to
    // registers (R16's unroll-1 version demoted these to local memory).
    float ax[APT], ay[APT], aal[APT];
    float4 c4[APT];
    #pragma unroll
    for (int k = 0; k < APT; k++) {
        const int a = t + k * TPS;
        ax[k]  = anc[3 * a + 0];
        ay[k]  = anc[3 * a + 1];
        aal[k] = anc[3 * a + 2];
        c4[k]  = *(const float4*)(cls + ((size_t)b * NUM_A + a) * NUM_C);
    }

    // Window lookups for all 4 anchors (independent LDS chains overlap).
    int p0v[APT], tripsv[APT];
    unsigned long long axx[APT], ayy[APT];
    #pragma unroll
    for (int k = 0; k < APT; k++) {
        unsigned xb = __float_as_uint(ax[k]), yb = __float_as_uint(ay[k]);
        PACK_F32X2(axx[k], xb, xb);
        PACK_F32X2(ayy[k], yb, yb);
        const int g = min((int)(ax[k] * 0.125f), NBKT - 1);
        const unsigned lut = s_lut[g];
        const int lo = (int)(lut & 0xffu);
        const int hi = (int)(lut >> 8);
        p0v[k]    = lo >> 1;
        tripsv[k] = ((hi + 1) >> 1) - p0v[k];   // pairs covering [lo, hi)
    }

    #pragma unroll
    for (int k = 0; k < APT; k++) {
        const int a = t + k * TPS;

        // Pruned argmin via bit-packed keys (positive-float bits u32-ordered;
        // low 6 bits carry the SORTED index; winner remapped via s_torig).
        // Superset-safe: every annotation with d<30 lies in the bucket window;
        // if the winner's exact d2 >= 900 the anchor is background and the
        // winner's identity never reaches the output.
        unsigned bestkey = 0xffffffffu;
        const int p0 = p0v[k], trips = tripsv[k];
        const ulonglong2* sp = (const ulonglong2*)s_sp;
        for (int j = 0; j < trips; j++) {       // SIMT predication = warp-max
            ulonglong2 q = sp[p0 + j];          // (-x0,-x1), (-y0,-y1)
            unsigned long long dxp, dyp, tp, d2p;
            ADD_F32X2(dxp, axx[k], q.x);        // (ax-x0, ax-x1)
            ADD_F32X2(dyp, ayy[k], q.y);
            MUL_F32X2(tp, dxp, dxp);
            FMA_F32X2(d2p, dyp, dyp, tp);       // == fmaf(dy,dy,dx*dx) per lane
            unsigned sj = (unsigned)(2 * (p0 + j));
            unsigned klo = ((unsigned)d2p & KMASK) | sj;
            unsigned khi = ((unsigned)(d2p >> 32) & KMASK) | (sj + 1u);
            bestkey = min(bestkey, min(klo, khi));
        }
        const int bestm = s_torig[bestkey & 63u];   // sorted -> original index

        // ---- epilogue: recompute EXACT values from original-order arrays ----
        const int bj = bestm >> 1, bslot = bestm & 1;
        const float bx  = -s_pair[4 * bj + bslot];
        const float by  = -s_pair[4 * bj + 2 + bslot];
        const float bal = s_al[bestm];
        const float ddx = ax[k] - bx;
        const float ddy = ay[k] - by;
        const float best = fmaf(ddy, ddy, ddx * ddx);
        const float dang = fabsf(aal[k] - bal);

        // sqrt-free thresholds: dxy<20 <=> d2<400 ; dxy>=30 <=> d2>=900
        const bool positive   = (best < 400.0f) && (dang < 15.0f);
        const bool background = (best >= 900.0f) || (dang >= 22.5f);
        const bool care       = positive || background;

        if (care) {
            int label = positive ? min(max((int)s_lb[bestm], 0), NUM_C - 1) : -1;
            float cv[4] = {c4[k].x, c4[k].y, c4[k].z, c4[k].w};
            #pragma unroll
            for (int c = 0; c < NUM_C; c++) {
                float p = fminf(fmaxf(cv[c], 1e-4f), 1.0f - 1e-4f);
                bool is1 = (c == label);
                // t==1: w = 0.95*(1-p)^2, bce = -log(p)
                // t==0: w = 0.05*p^2,     bce = -log(1-p)
                float q = is1 ? (1.0f - p) : p;
                float w = (is1 ? 0.95f : 0.05f) * q * q;
                float bce = -__logf(1.0f - q);
                v0 = fmaf(w, bce, v0);
            }
        }

        if (positive) {
            const float* r3 = reg + ((size_t)b * NUM_A + a) * 3;
            float tx = bx  - ax[k];
            float ty = by  - ay[k];
            float ta = bal - aal[k];
            float dxr = fabsf(tx - r3[0]);
            float dyr = fabsf(ty - r3[1]);
            const float inv9 = 1.0f / 9.0f;
            float lx = (dxr <= inv9) ? (4.5f * dxr * dxr) : (dxr - 0.5f * inv9);
            float ly = (dyr <= inv9) ? (4.5f * dyr * dyr) : (dyr - 0.5f * inv9);
            v1 += lx + ly;
            v2 += fmaxf((fabsf(ta - r3[2]) - 10.0f) * 0.2f, 0.0f);
            v3 += 1.0f;
        }
    }

    // ---- block reduction: 4 quantities ----
    #pragma unroll
    for (int o = 16; o > 0; o >>= 1) {
        v0 += __shfl_down_sync(0xffffffffu, v0, o);
        v1 += __shfl_down_sync(0xffffffffu, v1, o);
        v2 += __shfl_down_sync(0xffffffffu, v2, o);
        v3 += __shfl_down_sync(0xffffffffu, v3, o);
    }
    __shared__ float red[BLOCK / 32][4];
    const int wid = tid >> 5, lid = tid & 31;
    if (lid == 0) {
        red[wid][0] = v0; red[wid][1] = v1; red[wid][2] = v2; red[wid][3] = v3;
    }
    __syncthreads();
    if (tid < 4) {
        float s = 0.0f;
        #pragma unroll
        for (int w = 0; w < BLOCK / 32; w++) s += red[w][tid];
        ((float*)&g_part[(size_t)b * GRIDX + blockIdx.x])[tid] = s;
        __threadfence();   // publish partials before the ticket increment
    }
    __syncthreads();

    // ---- last-block finalize (fused, no extra launches) ----
    __shared__ bool is_last;
    if (tid == 0) {
        unsigned v = atomicAdd(&g_count, 1u);
        is_last = (v == NBLOCKS - 1);
    }
    __syncthreads();
    if (!is_last) return;
    if (tid == 0) g_count = 0;   // reset for next graph replay

    // 8 warps: warp w reduces sample b=w over its 128 partials.
    __shared__ float s_res[NUM_B][3];
    const int w = tid >> 5, l = tid & 31;
    float4 acc = make_float4(0.f, 0.f, 0.f, 0.f);
    #pragma unroll
    for (int kk = 0; kk < GRIDX / 32; kk++) {
        float4 p = g_part[(size_t)w * GRIDX + l + 32 * kk];
        acc.x += p.x; acc.y += p.y; acc.z += p.z; acc.w += p.w;
    }
    #pragma unroll
    for (int o = 16; o > 0; o >>= 1) {
        acc.x += __shfl_down_sync(0xffffffffu, acc.x, o);
        acc.y += __shfl_down_sync(0xffffffffu, acc.y, o);
        acc.z += __shfl_down_sync(0xffffffffu, acc.z, o);
        acc.w += __shfl_down_sync(0xffffffffu, acc.w, o);
    }
    if (l == 0) {
        float denom = fmaxf(acc.w, 1.0f);
        s_res[w][0] = acc.x / denom;
        s_res[w][1] = acc.y / (2.0f * denom);
        s_res[w][2] = acc.z / denom;
    }
    __syncthreads();
    if (tid == 0) {
        float c = 0.f, x = 0.f, an = 0.f;
        #pragma unroll
        for (int bb = 0; bb < NUM_B; bb++) {
            c += s_res[bb][0]; x += s_res[bb][1]; an += s_res[bb][2];
        }
        out[0] = c  * (1.0f / NUM_B);
        out[1] = x  * (1.0f / NUM_B);
        out[2] = an * (1.0f / NUM_B);
    }
}

extern "C" void kernel_launch(void* const* d_in, const int* in_sizes, int n_in,
                              void* d_out, int out_size) {
    (void)in_sizes; (void)n_in; (void)out_size;
    const float* cls = (const float*)d_in[0];   // (B, A, C)
    const float* reg = (const float*)d_in[1];   // (B, A, 3)
    const float* anc = (const float*)d_in[2];   // (1, A, 3)
    const float* ann = (const float*)d_in[3];   // (B, M, 4)
    float* out = (float*)d_out;

    dim3 grid(GRIDX, NUM_B);
    focal_fused_kernel<<<grid, BLOCK>>>(cls, reg, anc, ann, out);
}